// round 6
// baseline (speedup 1.0000x reference)
#include <cuda_runtime.h>

// GCN: h1 = relu(Agg(x@W1) + b1); h2 = relu(Agg(h1@W2) + b2); out = h2@Wr + br
// Agg = symmetric-normalized adjacency with self loops, built as dst-CSR per launch.

#define D_FEAT 128
#define MAXN 50000
#define MAXE 800000

// Scratch (static device globals — no allocation allowed).
__device__ float g_dinv[MAXN];
__device__ int   g_cnt[MAXN];
__device__ int   g_rowptr[MAXN];
__device__ int   g_cursor[MAXN];
__device__ int   g_src[MAXE];
__device__ __align__(16) float g_tmp[MAXN * D_FEAT];   // GEMM output (pre-aggregation)
__device__ __align__(16) float g_h[MAXN * D_FEAT];     // post-aggregation hidden state
__device__ int   g_is32;                               // edge_index dtype flag

// ---------------------------------------------------------------------------
// Edge-index dtype detection. JAX with default x64-disabled config silently
// downcasts jnp.int64 -> int32, so the device buffer may be int32 despite the
// reference saying int64. Read the first 8192 64-bit words: genuine int64
// node ids are all in [0, MAXN); packed int32 pairs give values >= 2^32
// whenever the high id != 0. Any out-of-range value => int32 layout.
// ---------------------------------------------------------------------------
__global__ void k_detect(const long long* __restrict__ ei, int lim) {
    __shared__ int bad;
    if (threadIdx.x == 0) bad = 0;
    __syncthreads();
    for (int i = threadIdx.x; i < lim; i += blockDim.x) {
        long long v = ei[i];
        if (v < 0 || v >= MAXN) bad = 1;   // benign race, any-write wins
    }
    __syncthreads();
    if (threadIdx.x == 0) g_is32 = bad;
}

__device__ __forceinline__ int edge_at(const void* ei, int idx) {
    if (g_is32) return ((const int*)ei)[idx];
    return (int)((const long long*)ei)[idx];
}

// ---------------------------------------------------------------------------
// CSR build. All edge-derived indices are bounds-guarded: a bad index must
// never become a wild generic atomic (that's a sticky err717, undebuggable);
// at worst it becomes a visible rel_err.
// ---------------------------------------------------------------------------
__global__ void k_zero_cnt(int n) {
    int i = blockIdx.x * blockDim.x + threadIdx.x;
    if (i < n) g_cnt[i] = 0;
}

__global__ void k_count(const void* __restrict__ ei, int E, int n) {
    int e = blockIdx.x * blockDim.x + threadIdx.x;
    if (e < E) {
        int d = edge_at(ei, E + e);   // dst row
        if ((unsigned)d < (unsigned)n) atomicAdd(&g_cnt[d], 1);
    }
}

// Single-block exclusive scan over N=50k counts; also computes deg_inv_sqrt
// (deg = in-degree + 1 self loop, always > 0) and initializes fill cursors.
__global__ void k_scan(int n) {
    __shared__ int sh[1024];
    int t = threadIdx.x;
    int chunk = (n + 1023) / 1024;
    int s = t * chunk;
    int e = min(n, s + chunk);
    int run = 0;
    for (int i = s; i < e; i++) { g_rowptr[i] = run; run += g_cnt[i]; }
    sh[t] = run;
    __syncthreads();
    if (t == 0) {
        int acc = 0;
        for (int i = 0; i < 1024; i++) { int v = sh[i]; sh[i] = acc; acc += v; }
    }
    __syncthreads();
    int off = sh[t];
    for (int i = s; i < e; i++) {
        int r = g_rowptr[i] + off;
        g_rowptr[i] = r;
        g_cursor[i] = r;
        g_dinv[i] = rsqrtf((float)g_cnt[i] + 1.0f);
    }
}

__global__ void k_fill(const void* __restrict__ ei, int E, int n) {
    int e = blockIdx.x * blockDim.x + threadIdx.x;
    if (e < E) {
        int srcv = edge_at(ei, e);
        int d    = edge_at(ei, E + e);
        if ((unsigned)d < (unsigned)n && (unsigned)srcv < (unsigned)n) {
            int p = atomicAdd(&g_cursor[d], 1);
            if ((unsigned)p < (unsigned)MAXE) g_src[p] = srcv;
        }
    }
}

// ---------------------------------------------------------------------------
// SGEMM: g_tmp[n,128] = A[n,128] @ W[128,128]  (row-major, BM=64 rows/block,
// full N=128 per block, BK=16, thread tile 8x4, 256 threads).
// A is either the harness input x or the device-global g_h (selected by flag).
// ---------------------------------------------------------------------------
#define GBM 64
#define GBK 16
__global__ void __launch_bounds__(256) k_gemm(const float* __restrict__ Aext,
                                              int use_gh,
                                              const float* __restrict__ W,
                                              int n) {
    __shared__ float  As[GBM][GBK + 1];
    __shared__ float4 Bs[GBK * 32];

    const float* A = use_gh ? g_h : Aext;

    int tid = threadIdx.x;
    int tx = tid & 31;       // col group: cols [tx*4, tx*4+4)
    int ty = tid >> 5;       // row group: rows [ty*8, ty*8+8)
    int r0 = blockIdx.x * GBM;

    float acc[8][4];
#pragma unroll
    for (int i = 0; i < 8; i++)
#pragma unroll
        for (int j = 0; j < 4; j++) acc[i][j] = 0.0f;

    const float4* W4 = reinterpret_cast<const float4*>(W);

    for (int k0 = 0; k0 < D_FEAT; k0 += GBK) {
        // Load A tile: 64x16 floats
#pragma unroll
        for (int i = tid; i < GBM * GBK; i += 256) {
            int row = i >> 4, col = i & 15;
            int gr = r0 + row;
            As[row][col] = (gr < n) ? A[gr * D_FEAT + k0 + col] : 0.0f;
        }
        // Load W tile: 16x128 floats as float4
#pragma unroll
        for (int i = tid; i < GBK * 32; i += 256) {
            int kk = i >> 5, n4 = i & 31;
            Bs[i] = W4[(k0 + kk) * 32 + n4];
        }
        __syncthreads();

#pragma unroll
        for (int kk = 0; kk < GBK; kk++) {
            float4 b = Bs[kk * 32 + tx];
#pragma unroll
            for (int i = 0; i < 8; i++) {
                float a = As[ty * 8 + i][kk];
                acc[i][0] += a * b.x;
                acc[i][1] += a * b.y;
                acc[i][2] += a * b.z;
                acc[i][3] += a * b.w;
            }
        }
        __syncthreads();
    }

    float4* C4 = reinterpret_cast<float4*>(g_tmp);
#pragma unroll
    for (int i = 0; i < 8; i++) {
        int gr = r0 + ty * 8 + i;
        if (gr < n)
            C4[gr * 32 + tx] = make_float4(acc[i][0], acc[i][1], acc[i][2], acc[i][3]);
    }
}

// ---------------------------------------------------------------------------
// Gather aggregation: one warp per dst node, lane owns 4 features (float4).
// g_h[d] = relu( dinv[d]^2 * tmp[d] + sum_{s in N(d)} dinv[s]*dinv[d]*tmp[s] + b )
// No float atomics; coalesced writes; random reads served by L2 (25.6MB set).
// ---------------------------------------------------------------------------
__global__ void __launch_bounds__(256) k_agg(const float* __restrict__ bias,
                                             int n) {
    int node = (blockIdx.x * blockDim.x + threadIdx.x) >> 5;
    int lane = threadIdx.x & 31;
    if (node >= n) return;

    const float4* t4 = reinterpret_cast<const float4*>(g_tmp);
    float dn = g_dinv[node];
    float4 v = t4[node * 32 + lane];
    float w0 = dn * dn;
    float4 acc = make_float4(w0 * v.x, w0 * v.y, w0 * v.z, w0 * v.w);

    int st = g_rowptr[node];
    int deg = g_cnt[node];
    for (int j = 0; j < deg; j++) {
        int s = g_src[st + j];
        float w = g_dinv[s] * dn;
        float4 u = t4[s * 32 + lane];
        acc.x += w * u.x; acc.y += w * u.y; acc.z += w * u.z; acc.w += w * u.w;
    }

    float4 b = reinterpret_cast<const float4*>(bias)[lane];
    acc.x = fmaxf(acc.x + b.x, 0.0f);
    acc.y = fmaxf(acc.y + b.y, 0.0f);
    acc.z = fmaxf(acc.z + b.z, 0.0f);
    acc.w = fmaxf(acc.w + b.w, 0.0f);
    reinterpret_cast<float4*>(g_h)[node * 32 + lane] = acc;
}

// ---------------------------------------------------------------------------
// Regression head: out[n] = dot(g_h[n], Wr) + br. One warp per node.
// ---------------------------------------------------------------------------
__global__ void __launch_bounds__(256) k_final(const float* __restrict__ Wr,
                                               const float* __restrict__ br,
                                               float* __restrict__ out, int n) {
    int node = (blockIdx.x * blockDim.x + threadIdx.x) >> 5;
    int lane = threadIdx.x & 31;
    if (node >= n) return;
    float4 a = reinterpret_cast<const float4*>(g_h)[node * 32 + lane];
    float4 w = reinterpret_cast<const float4*>(Wr)[lane];
    float s = a.x * w.x + a.y * w.y + a.z * w.z + a.w * w.w;
#pragma unroll
    for (int o = 16; o; o >>= 1) s += __shfl_xor_sync(0xffffffffu, s, o);
    if (lane == 0) out[node] = s + br[0];
}

// ---------------------------------------------------------------------------
// Launch
// Inputs: 0:x [N,128] f32, 1:edge_index [2,E] int32 or int64, 2:W1 [128,128],
//         3:b1 [128], 4:W2 [128,128], 5:b2 [128], 6:Wr [128,1], 7:br [1]
// ---------------------------------------------------------------------------
extern "C" void kernel_launch(void* const* d_in, const int* in_sizes, int n_in,
                              void* d_out, int out_size) {
    const float* x  = (const float*)d_in[0];
    const void*  ei = d_in[1];
    const float* W1 = (const float*)d_in[2];
    const float* b1 = (const float*)d_in[3];
    const float* W2 = (const float*)d_in[4];
    const float* b2 = (const float*)d_in[5];
    const float* Wr = (const float*)d_in[6];
    const float* br = (const float*)d_in[7];
    float* out = (float*)d_out;

    int N = in_sizes[0] / D_FEAT;
    int E = in_sizes[1] / 2;

    int nb_n  = (N + 255) / 256;
    int nb_e  = (E + 255) / 256;
    int nb_g  = (N + GBM - 1) / GBM;
    int nb_w  = (N + 7) / 8;          // 8 warps per 256-thread block

    // Dtype probe: reads 8192 int64 words = 64KB, in-bounds for either layout.
    k_detect<<<1, 256>>>((const long long*)ei, 8192);

    // CSR build (shared by both layers)
    k_zero_cnt<<<nb_n, 256>>>(N);
    k_count<<<nb_e, 256>>>(ei, E, N);
    k_scan<<<1, 1024>>>(N);
    k_fill<<<nb_e, 256>>>(ei, E, N);

    // Layer 1: tmp = x@W1 ; h = relu(Agg(tmp)+b1)
    k_gemm<<<nb_g, 256>>>(x, 0, W1, N);
    k_agg<<<nb_w, 256>>>(b1, N);

    // Layer 2: tmp = h@W2 ; h = relu(Agg(tmp)+b2)
    k_gemm<<<nb_g, 256>>>(nullptr, 1, W2, N);
    k_agg<<<nb_w, 256>>>(b2, N);

    // Head
    k_final<<<nb_w, 256>>>(Wr, br, out, N);
}

// round 7
// speedup vs baseline: 1.7738x; 1.7738x over previous
#include <cuda_runtime.h>

// GCN: h1 = relu(Agg(x@W1) + b1); h2 = relu(Agg(h1@W2) + b2); out = h2@Wr + br
// Agg = symmetric-normalized adjacency with self loops, built as dst-CSR per launch.

#define D_FEAT 128
#define MAXN 50000
#define MAXE 800000
#define SCAN_B 1024                      // elements per scan block
#define MAXBLK ((MAXN + SCAN_B - 1) / SCAN_B)

// Scratch (static device globals — no allocation allowed).
__device__ float g_dinv[MAXN];
__device__ int   g_cnt[MAXN];
__device__ int   g_rowptr[MAXN];
__device__ int   g_cursor[MAXN];
__device__ int   g_src[MAXE];
__device__ int   g_bsum[MAXBLK + 1];
__device__ __align__(16) float g_tmp[MAXN * D_FEAT];   // GEMM output (pre-aggregation)
__device__ __align__(16) float g_h[MAXN * D_FEAT];     // post-aggregation hidden state
__device__ int   g_is32;                               // edge_index dtype flag

// ---------------------------------------------------------------------------
// Edge-index dtype detection (JAX x64-disabled silently stores int32).
// ---------------------------------------------------------------------------
__global__ void k_detect(const long long* __restrict__ ei, int lim) {
    __shared__ int bad;
    if (threadIdx.x == 0) bad = 0;
    __syncthreads();
    for (int i = threadIdx.x; i < lim; i += blockDim.x) {
        long long v = ei[i];
        if (v < 0 || v >= MAXN) bad = 1;   // benign race
    }
    __syncthreads();
    if (threadIdx.x == 0) g_is32 = bad;
}

__device__ __forceinline__ int edge_at(const void* ei, int idx) {
    if (g_is32) return ((const int*)ei)[idx];
    return (int)((const long long*)ei)[idx];
}

// ---------------------------------------------------------------------------
// CSR build. Bounds-guarded so a bad index can never become a wild atomic.
// ---------------------------------------------------------------------------
__global__ void k_zero_cnt(int n) {
    int i = blockIdx.x * blockDim.x + threadIdx.x;
    if (i < n) g_cnt[i] = 0;
}

__global__ void k_count(const void* __restrict__ ei, int E, int n) {
    int e = blockIdx.x * blockDim.x + threadIdx.x;
    if (e < E) {
        int d = edge_at(ei, E + e);   // dst row
        if ((unsigned)d < (unsigned)n) atomicAdd(&g_cnt[d], 1);
    }
}

// --- Parallel exclusive scan of g_cnt, 3 passes -----------------------------
// Pass 1: block-local exclusive scan via warp shuffles; block totals -> g_bsum.
__global__ void __launch_bounds__(SCAN_B) k_scan1(int n) {
    __shared__ int wsum[32];
    int tid = threadIdx.x;
    int lane = tid & 31, wid = tid >> 5;
    int i = blockIdx.x * SCAN_B + tid;
    int v = (i < n) ? g_cnt[i] : 0;

    int incl = v;
#pragma unroll
    for (int o = 1; o < 32; o <<= 1) {
        int t = __shfl_up_sync(0xffffffffu, incl, o);
        if (lane >= o) incl += t;
    }
    if (lane == 31) wsum[wid] = incl;
    __syncthreads();
    if (wid == 0) {
        int w = wsum[lane];
        int wi = w;
#pragma unroll
        for (int o = 1; o < 32; o <<= 1) {
            int t = __shfl_up_sync(0xffffffffu, wi, o);
            if (lane >= o) wi += t;
        }
        wsum[lane] = wi - w;   // exclusive warp offsets
    }
    __syncthreads();
    int excl = incl - v + wsum[wid];
    if (i < n) g_rowptr[i] = excl;          // block-local for now
    if (tid == SCAN_B - 1) g_bsum[blockIdx.x] = excl + v;
}

// Pass 2: scan the ~49 block totals (single tiny block; smem-resident).
__global__ void k_scan2(int nb) {
    __shared__ int s[MAXBLK];
    int tid = threadIdx.x;
    if (tid < nb) s[tid] = g_bsum[tid];
    __syncthreads();
    if (tid == 0) {
        int acc = 0;
        for (int i = 0; i < nb; i++) { int t = s[i]; s[i] = acc; acc += t; }
    }
    __syncthreads();
    if (tid < nb) g_bsum[tid] = s[tid];
}

// Pass 3: add block offsets; init cursors and deg_inv_sqrt (deg = cnt+1 self loop).
__global__ void k_scan3(int n) {
    int i = blockIdx.x * blockDim.x + threadIdx.x;
    if (i < n) {
        int r = g_rowptr[i] + g_bsum[i >> 10];
        g_rowptr[i] = r;
        g_cursor[i] = r;
        g_dinv[i] = rsqrtf((float)g_cnt[i] + 1.0f);
    }
}

__global__ void k_fill(const void* __restrict__ ei, int E, int n) {
    int e = blockIdx.x * blockDim.x + threadIdx.x;
    if (e < E) {
        int srcv = edge_at(ei, e);
        int d    = edge_at(ei, E + e);
        if ((unsigned)d < (unsigned)n && (unsigned)srcv < (unsigned)n) {
            int p = atomicAdd(&g_cursor[d], 1);
            if ((unsigned)p < (unsigned)MAXE) g_src[p] = srcv;
        }
    }
}

// ---------------------------------------------------------------------------
// SGEMM: g_tmp[n,128] = A[n,128] @ W[128,128]  (BM=64, BK=16, 8x4/thread).
// ---------------------------------------------------------------------------
#define GBM 64
#define GBK 16
__global__ void __launch_bounds__(256) k_gemm(const float* __restrict__ Aext,
                                              int use_gh,
                                              const float* __restrict__ W,
                                              int n) {
    __shared__ float  As[GBM][GBK + 1];
    __shared__ float4 Bs[GBK * 32];

    const float* A = use_gh ? g_h : Aext;

    int tid = threadIdx.x;
    int tx = tid & 31;
    int ty = tid >> 5;
    int r0 = blockIdx.x * GBM;

    float acc[8][4];
#pragma unroll
    for (int i = 0; i < 8; i++)
#pragma unroll
        for (int j = 0; j < 4; j++) acc[i][j] = 0.0f;

    const float4* W4 = reinterpret_cast<const float4*>(W);

    for (int k0 = 0; k0 < D_FEAT; k0 += GBK) {
#pragma unroll
        for (int i = tid; i < GBM * GBK; i += 256) {
            int row = i >> 4, col = i & 15;
            int gr = r0 + row;
            As[row][col] = (gr < n) ? A[gr * D_FEAT + k0 + col] : 0.0f;
        }
#pragma unroll
        for (int i = tid; i < GBK * 32; i += 256) {
            int kk = i >> 5, n4 = i & 31;
            Bs[i] = W4[(k0 + kk) * 32 + n4];
        }
        __syncthreads();

#pragma unroll
        for (int kk = 0; kk < GBK; kk++) {
            float4 b = Bs[kk * 32 + tx];
#pragma unroll
            for (int i = 0; i < 8; i++) {
                float a = As[ty * 8 + i][kk];
                acc[i][0] += a * b.x;
                acc[i][1] += a * b.y;
                acc[i][2] += a * b.z;
                acc[i][3] += a * b.w;
            }
        }
        __syncthreads();
    }

    float4* C4 = reinterpret_cast<float4*>(g_tmp);
#pragma unroll
    for (int i = 0; i < 8; i++) {
        int gr = r0 + ty * 8 + i;
        if (gr < n)
            C4[gr * 32 + tx] = make_float4(acc[i][0], acc[i][1], acc[i][2], acc[i][3]);
    }
}

// ---------------------------------------------------------------------------
// Gather aggregation: one warp per dst node, lane owns 4 features (float4).
// acc = relu( dinv[d]^2*tmp[d] + sum_s dinv[s]*dinv[d]*tmp[s] + b )
// head==0: write acc to g_h.   head==1: fused regression head:
//   out[node] = dot(acc, Wr) + br (warp shuffle reduce), g_h not written.
// ---------------------------------------------------------------------------
__global__ void __launch_bounds__(256) k_agg(const float* __restrict__ bias,
                                             const float* __restrict__ Wr,
                                             const float* __restrict__ br,
                                             float* __restrict__ out,
                                             int n, int head) {
    int node = (blockIdx.x * blockDim.x + threadIdx.x) >> 5;
    int lane = threadIdx.x & 31;
    if (node >= n) return;

    const float4* t4 = reinterpret_cast<const float4*>(g_tmp);
    float dn = g_dinv[node];
    float4 v = t4[node * 32 + lane];
    float w0 = dn * dn;
    float4 acc = make_float4(w0 * v.x, w0 * v.y, w0 * v.z, w0 * v.w);

    int st = g_rowptr[node];
    int deg = g_cnt[node];
    for (int j = 0; j < deg; j++) {
        int s = g_src[st + j];
        float w = g_dinv[s] * dn;
        float4 u = t4[s * 32 + lane];
        acc.x += w * u.x; acc.y += w * u.y; acc.z += w * u.z; acc.w += w * u.w;
    }

    float4 b = reinterpret_cast<const float4*>(bias)[lane];
    acc.x = fmaxf(acc.x + b.x, 0.0f);
    acc.y = fmaxf(acc.y + b.y, 0.0f);
    acc.z = fmaxf(acc.z + b.z, 0.0f);
    acc.w = fmaxf(acc.w + b.w, 0.0f);

    if (!head) {
        reinterpret_cast<float4*>(g_h)[node * 32 + lane] = acc;
    } else {
        float4 w = reinterpret_cast<const float4*>(Wr)[lane];
        float s = acc.x * w.x + acc.y * w.y + acc.z * w.z + acc.w * w.w;
#pragma unroll
        for (int o = 16; o; o >>= 1) s += __shfl_xor_sync(0xffffffffu, s, o);
        if (lane == 0) out[node] = s + br[0];
    }
}

// ---------------------------------------------------------------------------
// Launch
// Inputs: 0:x [N,128] f32, 1:edge_index [2,E] int32 or int64, 2:W1, 3:b1,
//         4:W2, 5:b2, 6:Wr [128,1], 7:br [1]
// ---------------------------------------------------------------------------
extern "C" void kernel_launch(void* const* d_in, const int* in_sizes, int n_in,
                              void* d_out, int out_size) {
    const float* x  = (const float*)d_in[0];
    const void*  ei = d_in[1];
    const float* W1 = (const float*)d_in[2];
    const float* b1 = (const float*)d_in[3];
    const float* W2 = (const float*)d_in[4];
    const float* b2 = (const float*)d_in[5];
    const float* Wr = (const float*)d_in[6];
    const float* br = (const float*)d_in[7];
    float* out = (float*)d_out;

    int N = in_sizes[0] / D_FEAT;
    int E = in_sizes[1] / 2;

    int nb_n = (N + 255) / 256;
    int nb_e = (E + 255) / 256;
    int nb_g = (N + GBM - 1) / GBM;
    int nb_w = (N + 7) / 8;                 // 8 warps per 256-thread block
    int nb_s = (N + SCAN_B - 1) / SCAN_B;   // scan blocks

    // Dtype probe (64KB read, in-bounds for either layout).
    k_detect<<<1, 256>>>((const long long*)ei, 8192);

    // CSR build (shared by both layers)
    k_zero_cnt<<<nb_n, 256>>>(N);
    k_count<<<nb_e, 256>>>(ei, E, N);
    k_scan1<<<nb_s, SCAN_B>>>(N);
    k_scan2<<<1, 64>>>(nb_s);
    k_scan3<<<nb_n, 256>>>(N);
    k_fill<<<nb_e, 256>>>(ei, E, N);

    // Layer 1: tmp = x@W1 ; h = relu(Agg(tmp)+b1)
    k_gemm<<<nb_g, 256>>>(x, 0, W1, N);
    k_agg<<<nb_w, 256>>>(b1, Wr, br, out, N, 0);

    // Layer 2: tmp = h@W2 ; out = relu(Agg(tmp)+b2) @ Wr + br  (fused head)
    k_gemm<<<nb_g, 256>>>(nullptr, 1, W2, N);
    k_agg<<<nb_w, 256>>>(b2, Wr, br, out, N, 1);
}